// round 5
// baseline (speedup 1.0000x reference)
#include <cuda_runtime.h>
#include <math.h>

// Problem constants (fixed by reference)
#define BATCH   2
#define NFACES  4096
#define IS      256
#define NPIX    (IS*IS)
#define TPD     16              // tiles per dimension (16x16-pixel tiles)
#define NTILES  (TPD*TPD)       // 256 tiles per batch image
#define RECSZ   24              // floats per precomputed face record (6 x float4)
#define FARV    100.0f
#define NEARV   0.1f

// Scratch (static device globals — no dynamic allocation allowed).
// g_rec   : per-face precomputed record:
//   q0 = {e0x, e0y, e0c, z0}   edge 0->1 coeffs (edge = ex*xp + ey*yp + ec), vertex z0
//   q1 = {e1x, e1y, e1c, z1}   edge 1->2
//   q2 = {e2x, e2y, e2c, z2}   edge 2->0
//   q3 = {i00, i01, i02, 1/z0} barycentric inverse row 0 (already / det)
//   q4 = {i10, i11, i12, 1/z1}
//   q5 = {i20, i21, i22, 1/z2}
__device__ float g_rec[BATCH*NFACES*RECSZ];
__device__ int   g_cnt[BATCH*NTILES];
__device__ int   g_list[BATCH*NTILES*NFACES];   // 8 MB; per-tile capacity NFACES can't overflow

__global__ void reset_kernel() {
    int i = blockIdx.x*blockDim.x + threadIdx.x;
    if (i < BATCH*NTILES) g_cnt[i] = 0;
}

// One thread per (batch, face): precompute record + bin into overlapped tiles.
__global__ void bin_kernel(const float* __restrict__ faces) {
    int gid = blockIdx.x*blockDim.x + threadIdx.x;
    if (gid >= BATCH*NFACES) return;
    int b = gid / NFACES;
    int f = gid - b*NFACES;

    const float* fp = faces + (size_t)gid*9;
    float x0=fp[0], y0=fp[1], z0=fp[2];
    float x1=fp[3], y1=fp[4], z1=fp[5];
    float x2=fp[6], y2=fp[7], z2=fp[8];

    float det  = x2*(y0-y1) + x0*(y1-y2) + x1*(y2-y0);
    float detc = (det >= 0.f) ? fmaxf(det, 1e-10f) : fminf(det, -1e-10f);

    float* r = g_rec + (size_t)gid*RECSZ;
    // edge(a->b) evaluated at (xp,yp): (yp-ya)*(xb-xa) - (xp-xa)*(yb-ya)
    //   = (-(yb-ya))*xp + (xb-xa)*yp + (xa*(yb-ya) - ya*(xb-xa))
    { float dX=x1-x0, dY=y1-y0; r[0]=-dY; r[1]=dX; r[2]=x0*dY - y0*dX; r[3]=z0; }
    { float dX=x2-x1, dY=y2-y1; r[4]=-dY; r[5]=dX; r[6]=x1*dY - y1*dX; r[7]=z1; }
    { float dX=x0-x2, dY=y0-y2; r[8]=-dY; r[9]=dX; r[10]=x2*dY - y2*dX; r[11]=z2; }
    r[12]=(y1-y2)/detc; r[13]=(x2-x1)/detc; r[14]=(x1*y2-x2*y1)/detc; r[15]=1.0f/z0;
    r[16]=(y2-y0)/detc; r[17]=(x0-x2)/detc; r[18]=(x2*y0-x0*y2)/detc; r[19]=1.0f/z1;
    r[20]=(y0-y1)/detc; r[21]=(x1-x0)/detc; r[22]=(x0*y1-x1*y0)/detc; r[23]=1.0f/z2;

    // Winding cull: e0+e1+e2 == det identically, so all-edges>=0 (the reference's
    // "inside") is impossible when det < 0. det == 0 is measure-zero for random
    // float inputs.
    if (det <= 0.f) return;

    // Conservative pixel bbox. xp(ix) = (2*ix+1-256)/256, yp(row) = (255-2*row)/256.
    float xmn = fminf(x0, fminf(x1,x2)), xmx = fmaxf(x0, fmaxf(x1,x2));
    float ymn = fminf(y0, fminf(y1,y2)), ymx = fmaxf(y0, fmaxf(y1,y2));
    int ix0 = (int)floorf((256.f*xmn + 255.f)*0.5f) - 1;
    int ix1 = (int)ceilf ((256.f*xmx + 255.f)*0.5f) + 1;
    int iy0 = (int)floorf((255.f - 256.f*ymx)*0.5f) - 1;
    int iy1 = (int)ceilf ((255.f - 256.f*ymn)*0.5f) + 1;
    if (ix1 < 0 || ix0 > IS-1 || iy1 < 0 || iy0 > IS-1) return;
    ix0 = max(ix0, 0); ix1 = min(ix1, IS-1);
    iy0 = max(iy0, 0); iy1 = min(iy1, IS-1);

    int tx0 = ix0 >> 4, tx1 = ix1 >> 4;
    int ty0 = iy0 >> 4, ty1 = iy1 >> 4;
    for (int ty = ty0; ty <= ty1; ty++)
        for (int tx = tx0; tx <= tx1; tx++) {
            int t = b*NTILES + ty*TPD + tx;
            int pos = atomicAdd(&g_cnt[t], 1);
            if (pos < NFACES)                       // defensive: structurally can't overflow
                g_list[(size_t)t*NFACES + pos] = f;
        }
}

// One block per (tile, batch), one thread per pixel of the 16x16 tile.
__global__ void __launch_bounds__(256) render_kernel(
        const float* __restrict__ tex, float* __restrict__ out) {
    int tile = blockIdx.x;
    int b    = blockIdx.y;
    int tx = tile & (TPD-1), ty = tile >> 4;
    int lx = threadIdx.x & 15, ly = threadIdx.x >> 4;
    int px = (tx<<4) + lx, py = (ty<<4) + ly;

    float xp =  (2.f*(float)px + 1.f - (float)IS) * (1.f/(float)IS);
    float yp = -(2.f*(float)py + 1.f - (float)IS) * (1.f/(float)IS);

    int cnt = min(g_cnt[b*NTILES + tile], NFACES);
    const int* list = g_list + (size_t)(b*NTILES + tile)*NFACES;

    float bestZ = FARV;
    int   bestF = -1;
    float bw0=0.f, bw1=0.f, bw2=0.f, bws=1.f;   // clipped (unnormalized) weights + their sum

    for (int i = 0; i < cnt; i++) {
        int f = __ldg(list + i);                                  // uniform across warp
        const float4* R = (const float4*)(g_rec + (size_t)(b*NFACES+f)*RECSZ);
        float4 q0 = __ldg(R+0), q1 = __ldg(R+1), q2 = __ldg(R+2);
        float e0 = fmaf(q0.x, xp, fmaf(q0.y, yp, q0.z));
        float e1 = fmaf(q1.x, xp, fmaf(q1.y, yp, q1.z));
        float e2 = fmaf(q2.x, xp, fmaf(q2.y, yp, q2.z));
        if (!(e0 >= 0.f && e1 >= 0.f && e2 >= 0.f)) continue;

        float4 q3 = __ldg(R+3), q4 = __ldg(R+4), q5 = __ldg(R+5);
        float w0 = __saturatef(fmaf(q3.x, xp, fmaf(q3.y, yp, q3.z)));
        float w1 = __saturatef(fmaf(q4.x, xp, fmaf(q4.y, yp, q4.z)));
        float w2 = __saturatef(fmaf(q5.x, xp, fmaf(q5.y, yp, q5.z)));
        float ws = fmaxf(w0 + w1 + w2, 1e-10f);
        // Reference: wn = w/ws; inv_zp = sum(wn/z); zp = 1/max(inv_zp, 1e-10).
        // Equivalent single-division form: zp = ws / sum(w * (1/z)).
        float s  = fmaf(w0, q3.w, fmaf(w1, q4.w, w2*q5.w));
        float zp = ws / s;                       // s<=0 -> inf/NaN -> fails range test
        if (zp > NEARV && zp < FARV) {
            if (zp < bestZ || (zp == bestZ && (unsigned)f < (unsigned)bestF)) {
                bestZ = zp; bestF = f;
                bw0 = w0; bw1 = w1; bw2 = w2; bws = ws;
            }
        }
    }

    // Trilinear texture sampling of the winning face (T = 4).
    float cr = 0.f, cg = 0.f, cb = 0.f, alpha = 0.f;
    if (bestF >= 0) {
        alpha = 1.f;
        const float4* R = (const float4*)(g_rec + (size_t)(b*NFACES+bestF)*RECSZ);
        float rz0 = __ldg(R+3).w, rz1 = __ldg(R+4).w, rz2 = __ldg(R+5).w;
        float inws = 1.f / bws;
        float zt = 3.f * bestZ;                  // (T-1) * zp
        float t0 = fminf(fmaxf(bw0*inws * zt * rz0, 0.f), 2.999f);   // T-1-EPS
        float t1 = fminf(fmaxf(bw1*inws * zt * rz1, 0.f), 2.999f);
        float t2 = fminf(fmaxf(bw2*inws * zt * rz2, 0.f), 2.999f);
        int i0 = (int)t0, i1 = (int)t1, i2 = (int)t2;                // t>=0: trunc==floor
        float f0 = t0 - (float)i0, f1 = t1 - (float)i1, f2 = t2 - (float)i2;
        float a0 = 1.f - f0, a1 = 1.f - f1, a2 = 1.f - f2;
        const float* tb = tex + (size_t)(b*NFACES + bestF)*192;      // 4*4*4*3
        #pragma unroll
        for (int pn = 0; pn < 8; pn++) {
            int b0 = pn & 1, b1 = (pn>>1) & 1, b2 = (pn>>2) & 1;
            float wc = (b0 ? f0 : a0) * (b1 ? f1 : a1) * (b2 ? f2 : a2);
            int lin = ((i0+b0)*4 + (i1+b1))*4 + (i2+b2);
            const float* tp = tb + lin*3;
            cr = fmaf(wc, __ldg(tp+0), cr);
            cg = fmaf(wc, __ldg(tp+1), cg);
            cb = fmaf(wc, __ldg(tp+2), cb);
        }
    }

    // Output layout: rgb (B,256,256,3), then alpha (B,256,256), then zp (B,256,256).
    size_t p = (size_t)b*NPIX + (size_t)py*IS + px;
    out[p*3 + 0] = cr;
    out[p*3 + 1] = cg;
    out[p*3 + 2] = cb;
    out[(size_t)BATCH*NPIX*3 + p] = alpha;
    out[(size_t)BATCH*NPIX*4 + p] = bestZ;
}

extern "C" void kernel_launch(void* const* d_in, const int* in_sizes, int n_in,
                              void* d_out, int out_size) {
    const float* faces = (const float*)d_in[0];     // (2, 4096, 3, 3) f32
    const float* tex   = (const float*)d_in[1];     // (2, 4096, 4, 4, 4, 3) f32
    float* out = (float*)d_out;                     // 655360 f32: rgb | alpha | zp

    reset_kernel<<<1, BATCH*NTILES>>>();
    bin_kernel<<<(BATCH*NFACES + 127)/128, 128>>>(faces);
    render_kernel<<<dim3(NTILES, BATCH), 256>>>(tex, out);
}